// round 6
// baseline (speedup 1.0000x reference)
#include <cuda_runtime.h>
#include <math.h>
#include <float.h>

#define BATCH   4096
#define NPART   100
#define PSIZE   64
#define CTX     64
#define H1      256
#define H2      256
#define F3IN    320
#define F3OUT   512
#define F4OUT   256
#define F5OUT   128
#define F6OUT   32
#define HID     32
#define NLAYER  6
#define VOCAB   361
#define TSTEPS  24
#define TOPK    8

// scratch (device globals: allowed; no runtime allocation)
__device__ float g_pooled[BATCH * H2];   // 4 MB
__device__ float g_z[BATCH * F6OUT];     // 0.5 MB

// ---------------------------------------------------------------------------
// Kernel 1: particle encoder.  1 CTA per batch sample, 256 threads.
// ---------------------------------------------------------------------------
__global__ __launch_bounds__(256) void enc_kernel(
    const float* __restrict__ x,
    const float* __restrict__ w1, const float* __restrict__ b1,
    const float* __restrict__ w2, const float* __restrict__ b2)
{
    __shared__ float xs[NPART * PSIZE];   // 25600 B
    __shared__ float h1s[20 * H1];        // 20480 B (also reused as reduce buf)

    const int b   = blockIdx.x;
    const int tid = threadIdx.x;

    {
        const float4* xg  = (const float4*)(x + (size_t)b * (NPART * PSIZE));
        float4*       xs4 = (float4*)xs;
        for (int i = tid; i < NPART * PSIZE / 4; i += 256) xs4[i] = xg[i];
    }
    __syncthreads();

    const int jg = tid & 63;        // 0..63
    const int pg = tid >> 6;        // 0..3
    const int j0 = jg * 4;

    const float4 b1v = *(const float4*)(b1 + j0);
    const float4 b2v = *(const float4*)(b2 + j0);

    float4 pool = make_float4(0.f, 0.f, 0.f, 0.f);

    for (int chunk = 0; chunk < 5; chunk++) {
        const int lp0   = pg * 5;
        const int pbase = chunk * 20 + lp0;

        // ---- fc1 ----
        float4 a[5];
        #pragma unroll
        for (int p = 0; p < 5; p++) a[p] = b1v;

        #pragma unroll 8
        for (int k = 0; k < PSIZE; k++) {
            const float4 w = *(const float4*)(w1 + k * H1 + j0);
            #pragma unroll
            for (int p = 0; p < 5; p++) {
                const float xv = xs[(pbase + p) * PSIZE + k];
                a[p].x = fmaf(xv, w.x, a[p].x);
                a[p].y = fmaf(xv, w.y, a[p].y);
                a[p].z = fmaf(xv, w.z, a[p].z);
                a[p].w = fmaf(xv, w.w, a[p].w);
            }
        }
        #pragma unroll
        for (int p = 0; p < 5; p++) {
            float4 r;
            r.x = fmaxf(a[p].x, 0.f);
            r.y = fmaxf(a[p].y, 0.f);
            r.z = fmaxf(a[p].z, 0.f);
            r.w = fmaxf(a[p].w, 0.f);
            *(float4*)(h1s + (lp0 + p) * H1 + j0) = r;
        }
        __syncthreads();

        // ---- fc2 + pooled relu accumulate ----
        float4 a2[5];
        #pragma unroll
        for (int p = 0; p < 5; p++) a2[p] = b2v;

        #pragma unroll 8
        for (int k = 0; k < H1; k++) {
            const float4 w = *(const float4*)(w2 + k * H1 + j0);
            #pragma unroll
            for (int p = 0; p < 5; p++) {
                const float hv = h1s[(lp0 + p) * H1 + k];
                a2[p].x = fmaf(hv, w.x, a2[p].x);
                a2[p].y = fmaf(hv, w.y, a2[p].y);
                a2[p].z = fmaf(hv, w.z, a2[p].z);
                a2[p].w = fmaf(hv, w.w, a2[p].w);
            }
        }
        #pragma unroll
        for (int p = 0; p < 5; p++) {
            pool.x += fmaxf(a2[p].x, 0.f);
            pool.y += fmaxf(a2[p].y, 0.f);
            pool.z += fmaxf(a2[p].z, 0.f);
            pool.w += fmaxf(a2[p].w, 0.f);
        }
        __syncthreads();
    }

    *(float4*)(h1s + pg * H1 + j0) = pool;
    __syncthreads();
    const float s = (h1s[tid] + h1s[256 + tid] + h1s[512 + tid] + h1s[768 + tid]) * 0.01f;
    g_pooled[(size_t)b * H2 + tid] = s;
}

// ---------------------------------------------------------------------------
// Kernel 2: fc3..fc6 head. 8 samples per CTA, 256 threads.
// ---------------------------------------------------------------------------
__global__ __launch_bounds__(256) void head_kernel(
    const float* __restrict__ c,
    const float* __restrict__ w3, const float* __restrict__ b3,
    const float* __restrict__ w4, const float* __restrict__ b4,
    const float* __restrict__ w5, const float* __restrict__ b5,
    const float* __restrict__ w6, const float* __restrict__ b6)
{
    __shared__ float zin[8 * F3IN];   // 10240 B
    __shared__ float h3 [8 * F3OUT];  // 16384 B
    __shared__ float h4 [8 * F4OUT];  //  8192 B
    __shared__ float h5 [8 * F5OUT];  //  4096 B

    const int bb  = blockIdx.x * 8;
    const int tid = threadIdx.x;

    for (int i = tid; i < 8 * CTX; i += 256) {
        const int s = i >> 6, k = i & 63;
        zin[s * F3IN + k] = c[(size_t)(bb + s) * CTX + k];
    }
    for (int i = tid; i < 8 * H2; i += 256) {
        const int s = i >> 8, k = i & 255;
        zin[s * F3IN + CTX + k] = g_pooled[(size_t)(bb + s) * H2 + k];
    }
    __syncthreads();

    // fc3: 320 -> 512
    {
        const int j0 = tid * 2;
        const float2 bv = *(const float2*)(b3 + j0);
        float2 acc[8];
        #pragma unroll
        for (int s = 0; s < 8; s++) acc[s] = bv;
        #pragma unroll 4
        for (int k = 0; k < F3IN; k++) {
            const float2 w = *(const float2*)(w3 + k * F3OUT + j0);
            #pragma unroll
            for (int s = 0; s < 8; s++) {
                const float zv = zin[s * F3IN + k];
                acc[s].x = fmaf(zv, w.x, acc[s].x);
                acc[s].y = fmaf(zv, w.y, acc[s].y);
            }
        }
        #pragma unroll
        for (int s = 0; s < 8; s++) {
            float2 r;
            r.x = fmaxf(acc[s].x, 0.f);
            r.y = fmaxf(acc[s].y, 0.f);
            *(float2*)(h3 + s * F3OUT + j0) = r;
        }
    }
    __syncthreads();

    // fc4: 512 -> 256
    {
        const float bv = b4[tid];
        float acc[8];
        #pragma unroll
        for (int s = 0; s < 8; s++) acc[s] = bv;
        #pragma unroll 8
        for (int k = 0; k < F3OUT; k++) {
            const float w = w4[k * F4OUT + tid];
            #pragma unroll
            for (int s = 0; s < 8; s++) acc[s] = fmaf(h3[s * F3OUT + k], w, acc[s]);
        }
        #pragma unroll
        for (int s = 0; s < 8; s++) h4[s * F4OUT + tid] = fmaxf(acc[s], 0.f);
    }
    __syncthreads();

    // fc5: 256 -> 128
    {
        const int j  = tid & 127;
        const int sh = tid >> 7;
        const float bv = b5[j];
        float acc[4];
        #pragma unroll
        for (int i = 0; i < 4; i++) acc[i] = bv;
        #pragma unroll 8
        for (int k = 0; k < F4OUT; k++) {
            const float w = w5[k * F5OUT + j];
            #pragma unroll
            for (int i = 0; i < 4; i++)
                acc[i] = fmaf(h4[(sh * 4 + i) * F4OUT + k], w, acc[i]);
        }
        #pragma unroll
        for (int i = 0; i < 4; i++) h5[(sh * 4 + i) * F5OUT + j] = fmaxf(acc[i], 0.f);
    }
    __syncthreads();

    // fc6: 128 -> 32
    {
        const int s = tid >> 5, j = tid & 31;
        float acc = b6[j];
        #pragma unroll 8
        for (int k = 0; k < F5OUT; k++)
            acc = fmaf(h5[s * F5OUT + k], w6[k * F6OUT + j], acc);
        g_z[(size_t)(bb + s) * F6OUT + j] = fmaxf(acc, 0.f);
    }
}

// ---------------------------------------------------------------------------
// Kernel 3: 24-step 6-layer LSTM rollout + logits + top-8 per step.
// Output written as FLOAT values of the indices (R5 diagnosis: comparator
// reads d_out as float32; int bit patterns read as denormals ~0 -> rel_err 1.0).
// ---------------------------------------------------------------------------
__device__ __forceinline__ float sigmoidf_(float v) { return 1.0f / (1.0f + expf(-v)); }

__global__ __launch_bounds__(256) void lstm_kernel(
    const float* __restrict__ hidden0, const float* __restrict__ cell0,
    const float* __restrict__ wih, const float* __restrict__ whh,
    const float* __restrict__ bih, const float* __restrict__ bhh,
    const float* __restrict__ w10, const float* __restrict__ b10,
    float* __restrict__ out)
{
    __shared__ float hst[NLAYER * 8 * HID];   // 6144 B
    __shared__ float cst[NLAYER * 8 * HID];   // 6144 B
    __shared__ float xb [8 * HID];            // 1024 B
    __shared__ float gsm[8 * 128];            // 4096 B
    __shared__ float lsm[8 * 368];            // 11776 B
    __shared__ float bsum[NLAYER * 128];      // 3072 B

    const int bbase = blockIdx.x * 8;
    const int tid   = threadIdx.x;

    for (int i = tid; i < NLAYER * 8 * HID; i += 256) {
        const int l = i >> 8;
        const int r = i & 255;
        hst[i] = hidden0[(size_t)l * BATCH * HID + (size_t)bbase * HID + r];
        cst[i] = cell0  [(size_t)l * BATCH * HID + (size_t)bbase * HID + r];
    }
    for (int i = tid; i < 8 * HID; i += 256) xb[i] = g_z[(size_t)bbase * HID + i];
    for (int i = tid; i < NLAYER * 128; i += 256) bsum[i] = bih[i] + bhh[i];
    __syncthreads();

    const int jg = tid & 31, sg = tid >> 5;
    const int j0 = jg * 4;
    const int lane = tid & 31, warp = tid >> 5;

    const float* inp = xb;   // scan carry

    for (int t = 0; t < TSTEPS; t++) {
        const float* lin = inp;
        for (int l = 0; l < NLAYER; l++) {
            float4 a = *(const float4*)(bsum + l * 128 + j0);
            const float* Wi = wih + (size_t)l * HID * 128;
            const float* Wh = whh + (size_t)l * HID * 128;
            const float* ip = lin + sg * HID;
            const float* hp = hst + l * 8 * HID + sg * HID;
            #pragma unroll
            for (int k = 0; k < HID; k++) {
                const float4 w = *(const float4*)(Wi + k * 128 + j0);
                const float xv = ip[k];
                a.x = fmaf(xv, w.x, a.x); a.y = fmaf(xv, w.y, a.y);
                a.z = fmaf(xv, w.z, a.z); a.w = fmaf(xv, w.w, a.w);
            }
            #pragma unroll
            for (int k = 0; k < HID; k++) {
                const float4 w = *(const float4*)(Wh + k * 128 + j0);
                const float hv = hp[k];
                a.x = fmaf(hv, w.x, a.x); a.y = fmaf(hv, w.y, a.y);
                a.z = fmaf(hv, w.z, a.z); a.w = fmaf(hv, w.w, a.w);
            }
            *(float4*)(gsm + sg * 128 + j0) = a;
            __syncthreads();

            {
                const int s = tid >> 5, u = tid & 31;
                const float ig = sigmoidf_(gsm[s * 128 + u]);
                const float fg = sigmoidf_(gsm[s * 128 + 32 + u]);
                const float gg = tanhf    (gsm[s * 128 + 64 + u]);
                const float og = sigmoidf_(gsm[s * 128 + 96 + u]);
                const int ci = l * 8 * HID + s * HID + u;
                const float cn = fmaf(fg, cst[ci], ig * gg);
                cst[ci] = cn;
                hst[ci] = og * tanhf(cn);
            }
            __syncthreads();
            lin = hst + l * 8 * HID;
        }
        inp = hst + 5 * 8 * HID;   // carry to next timestep

        // logits
        {
            const float* h5v = hst + 5 * 8 * HID;
            const int v  = tid;
            const int v2 = tid + 256;
            const bool has2 = (v2 < VOCAB);
            float acc[8], acc2[8];
            const float bv  = b10[v];
            const float bv2 = has2 ? b10[v2] : 0.f;
            #pragma unroll
            for (int s = 0; s < 8; s++) { acc[s] = bv; acc2[s] = bv2; }
            #pragma unroll
            for (int k = 0; k < HID; k++) {
                const float w  = w10[k * VOCAB + v];
                const float w2 = has2 ? w10[k * VOCAB + v2] : 0.f;
                #pragma unroll
                for (int s = 0; s < 8; s++) {
                    const float hv = h5v[s * HID + k];
                    acc[s]  = fmaf(hv, w,  acc[s]);
                    acc2[s] = fmaf(hv, w2, acc2[s]);
                }
            }
            #pragma unroll
            for (int s = 0; s < 8; s++) {
                lsm[s * 368 + v] = acc[s];
                if (has2) lsm[s * 368 + v2] = acc2[s];
            }
        }
        __syncthreads();

        // top-8: one warp per sample, stable tie-break (lower index wins)
        {
            const int s = warp;
            float vals[12];
            #pragma unroll
            for (int i = 0; i < 12; i++) {
                const int idx = lane + i * 32;
                vals[i] = (idx < VOCAB) ? lsm[s * 368 + idx] : -FLT_MAX;
            }
            const int obase = (bbase + s) * (TSTEPS * TOPK) + t * TOPK;
            #pragma unroll
            for (int r = 0; r < TOPK; r++) {
                float bvv = vals[0]; int bi = 0;
                #pragma unroll
                for (int i = 1; i < 12; i++)
                    if (vals[i] > bvv) { bvv = vals[i]; bi = i; }
                int gi = lane + bi * 32;
                #pragma unroll
                for (int off = 16; off; off >>= 1) {
                    const float ov = __shfl_xor_sync(0xffffffffu, bvv, off);
                    const int   oi = __shfl_xor_sync(0xffffffffu, gi,  off);
                    if (ov > bvv || (ov == bvv && oi < gi)) { bvv = ov; gi = oi; }
                }
                if (lane == 0) out[obase + r] = (float)gi;   // FLOAT output
                if ((gi & 31) == lane) vals[gi >> 5] = -FLT_MAX;
            }
        }
        __syncthreads();
    }
}

// ---------------------------------------------------------------------------
// Host: identify inputs BY SIZE (element count or bytes auto-detected).
// ---------------------------------------------------------------------------
extern "C" void kernel_launch(void* const* d_in, const int* in_sizes, int n_in,
                              void* d_out, int out_size)
{
    const float* C_=0; const float* X_=0; const float* HID0_=0; const float* CELL0_=0;
    const float* W1_=0; const float* B1_=0; const float* W2_=0; const float* B2_=0;
    const float* W3_=0; const float* B3_=0; const float* W4_=0; const float* B4_=0;
    const float* W5_=0; const float* B5_=0; const float* W6_=0; const float* B6_=0;
    const float* BIH_=0; const float* BHH_=0; const float* W10_=0; const float* B10_=0;

    int div = 1;
    for (int i = 0; i < n_in; i++) {
        if (in_sizes[i] == 26214400) { div = 1; break; }
        if (in_sizes[i] == 104857600) { div = 4; break; }
    }

    int n256 = 0, n786 = 0, n768 = 0, n24k = 0;
    int idx24k[2] = {-1, -1};
    int idx_fc10w = -1, idx_fc1w = -1;

    for (int i = 0; i < n_in; i++) {
        const long s = (long)in_sizes[i] / div;
        const float* p = (const float*)d_in[i];
        switch (s) {
            case 262144:   C_  = p; break;
            case 26214400: X_  = p; break;
            case 786432:   if (n786++ == 0) HID0_ = p; else CELL0_ = p; break;
            case 16384:    W1_ = p; idx_fc1w = i; break;
            case 256:      { if (n256 == 0) B1_ = p; else if (n256 == 1) B2_ = p;
                             else B4_ = p; n256++; } break;
            case 65536:    W2_ = p; break;
            case 163840:   W3_ = p; break;
            case 512:      B3_ = p; break;
            case 131072:   W4_ = p; break;
            case 32768:    W5_ = p; break;
            case 128:      B5_ = p; break;
            case 4096:     W6_ = p; break;
            case 32:       B6_ = p; break;
            case 24576:    if (n24k < 2) idx24k[n24k] = i; n24k++; break;
            case 768:      if (n768++ == 0) BIH_ = p; else BHH_ = p; break;
            case 11552:    W10_ = p; idx_fc10w = i; break;
            case 361:      B10_ = p; break;
            default: break; // particle_size scalar etc.
        }
    }

    const float* WIH_ = 0; const float* WHH_ = 0;
    if (n24k >= 2) {
        const bool alpha = (idx_fc10w >= 0 && idx_fc1w >= 0 && idx_fc10w < idx_fc1w);
        const int wih_idx = alpha ? idx24k[1] : idx24k[0];
        const int whh_idx = alpha ? idx24k[0] : idx24k[1];
        WIH_ = (const float*)d_in[wih_idx];
        WHH_ = (const float*)d_in[whh_idx];
    }

    if (!C_ || !X_ || !HID0_ || !CELL0_ || !W1_ || !B1_ || !W2_ || !B2_ ||
        !W3_ || !B3_ || !W4_ || !B4_ || !W5_ || !B5_ || !W6_ || !B6_ ||
        !WIH_ || !WHH_ || !BIH_ || !BHH_ || !W10_ || !B10_) {
        C_    = (const float*)d_in[0];  X_    = (const float*)d_in[1];
        HID0_ = (const float*)d_in[2];  CELL0_= (const float*)d_in[3];
        W1_   = (const float*)d_in[4];  B1_   = (const float*)d_in[5];
        W2_   = (const float*)d_in[6];  B2_   = (const float*)d_in[7];
        W3_   = (const float*)d_in[8];  B3_   = (const float*)d_in[9];
        W4_   = (const float*)d_in[10]; B4_   = (const float*)d_in[11];
        W5_   = (const float*)d_in[12]; B5_   = (const float*)d_in[13];
        W6_   = (const float*)d_in[14]; B6_   = (const float*)d_in[15];
        WIH_  = (const float*)d_in[16]; WHH_  = (const float*)d_in[17];
        BIH_  = (const float*)d_in[18]; BHH_  = (const float*)d_in[19];
        W10_  = (const float*)d_in[20]; B10_  = (const float*)d_in[21];
    }
    (void)out_size;

    enc_kernel<<<BATCH, 256>>>(X_, W1_, B1_, W2_, B2_);
    head_kernel<<<BATCH / 8, 256>>>(C_, W3_, B3_, W4_, B4_, W5_, B5_, W6_, B6_);
    lstm_kernel<<<BATCH / 8, 256>>>(HID0_, CELL0_, WIH_, WHH_, BIH_, BHH_,
                                    W10_, B10_, (float*)d_out);
}

// round 7
// speedup vs baseline: 1.0058x; 1.0058x over previous
#include <cuda_runtime.h>
#include <math.h>
#include <float.h>

#define BATCH   4096
#define NPART   100
#define PSIZE   64
#define CTX     64
#define H1      256
#define H2      256
#define F3IN    320
#define F3OUT   512
#define F4OUT   256
#define F5OUT   128
#define F6OUT   32
#define HID     32
#define NLAYER  6
#define VOCAB   361
#define TSTEPS  24
#define TOPK    8

typedef unsigned long long ull;

// scratch (device globals: allowed; no runtime allocation)
__device__ float g_pooled[BATCH * H2];   // 4 MB
__device__ float g_z[BATCH * F6OUT];     // 0.5 MB

// ---------------- f32x2 packed helpers (Blackwell FFMA2 path) --------------
__device__ __forceinline__ ull ffma2(ull a, ull b, ull c) {
    ull d;
    asm("fma.rn.f32x2 %0, %1, %2, %3;" : "=l"(d) : "l"(a), "l"(b), "l"(c));
    return d;
}
__device__ __forceinline__ ull pack_dup(float v) {
    ull d;
    unsigned r = __float_as_uint(v);
    asm("mov.b64 %0, {%1, %2};" : "=l"(d) : "r"(r), "r"(r));
    return d;
}
__device__ __forceinline__ float2 unpack2(ull v) {
    unsigned lo, hi;
    asm("mov.b64 {%0, %1}, %2;" : "=r"(lo), "=r"(hi) : "l"(v));
    return make_float2(__uint_as_float(lo), __uint_as_float(hi));
}

// ---------------------------------------------------------------------------
// Kernel 1: particle encoder, FFMA2 version.  1 CTA per sample, 256 threads.
// fc1: x scalar LDS + pack_dup (ALU) -> FFMA2.
// fc2: h1 stored DUPLICATED in smem -> LDS.64 gives packed broadcast directly.
// Results bitwise identical to scalar version (IEEE fma per lane, same order).
// ---------------------------------------------------------------------------
__global__ __launch_bounds__(256) void enc_kernel(
    const float* __restrict__ x,
    const float* __restrict__ w1, const float* __restrict__ b1,
    const float* __restrict__ w2, const float* __restrict__ b2)
{
    __shared__ float  xs[20 * PSIZE];    //  5120 B (current 20-particle chunk)
    __shared__ float2 h1d[20 * H1];      // 40960 B (h1 duplicated (v,v))

    const int b   = blockIdx.x;
    const int tid = threadIdx.x;
    const int jg  = tid & 63;            // 0..63 -> 4 j's
    const int pg  = tid >> 6;            // 0..3  -> 5 particles
    const int j0  = jg * 4;
    const int lp0 = pg * 5;

    const ull b1v01 = *(const ull*)(b1 + j0);
    const ull b1v23 = *(const ull*)(b1 + j0 + 2);
    const ull b2v01 = *(const ull*)(b2 + j0);
    const ull b2v23 = *(const ull*)(b2 + j0 + 2);

    float pool0 = 0.f, pool1 = 0.f, pool2 = 0.f, pool3 = 0.f;

    for (int chunk = 0; chunk < 5; chunk++) {
        // ---- stage 20 particles of x into smem (coalesced float4) ----
        {
            const float4* xg  = (const float4*)(x + (size_t)b * (NPART * PSIZE)
                                                + (size_t)chunk * 20 * PSIZE);
            float4* xs4 = (float4*)xs;
            for (int i = tid; i < 20 * PSIZE / 4; i += 256) xs4[i] = xg[i];
        }
        __syncthreads();

        // ---- fc1: 64 -> 256 over 5 particles ----
        ull a01[5], a23[5];
        #pragma unroll
        for (int p = 0; p < 5; p++) { a01[p] = b1v01; a23[p] = b1v23; }

        #pragma unroll 4
        for (int k = 0; k < PSIZE; k++) {
            const ulonglong2 w = *(const ulonglong2*)(w1 + k * H1 + j0);
            #pragma unroll
            for (int p = 0; p < 5; p++) {
                const ull xx = pack_dup(xs[(lp0 + p) * PSIZE + k]);
                a01[p] = ffma2(xx, w.x, a01[p]);
                a23[p] = ffma2(xx, w.y, a23[p]);
            }
        }
        #pragma unroll
        for (int p = 0; p < 5; p++) {
            const float2 v01 = unpack2(a01[p]);
            const float2 v23 = unpack2(a23[p]);
            float2* hr = h1d + (lp0 + p) * H1 + j0;
            const float r0 = fmaxf(v01.x, 0.f);
            const float r1 = fmaxf(v01.y, 0.f);
            const float r2 = fmaxf(v23.x, 0.f);
            const float r3 = fmaxf(v23.y, 0.f);
            hr[0] = make_float2(r0, r0);
            hr[1] = make_float2(r1, r1);
            hr[2] = make_float2(r2, r2);
            hr[3] = make_float2(r3, r3);
        }
        __syncthreads();

        // ---- fc2: 256 -> 256 over 5 particles, pooled relu accumulate ----
        ull c01[5], c23[5];
        #pragma unroll
        for (int p = 0; p < 5; p++) { c01[p] = b2v01; c23[p] = b2v23; }

        #pragma unroll 4
        for (int k = 0; k < H1; k++) {
            const ulonglong2 w = *(const ulonglong2*)(w2 + k * H1 + j0);
            #pragma unroll
            for (int p = 0; p < 5; p++) {
                const ull hh = *(const ull*)(h1d + (lp0 + p) * H1 + k); // (h,h)
                c01[p] = ffma2(hh, w.x, c01[p]);
                c23[p] = ffma2(hh, w.y, c23[p]);
            }
        }
        #pragma unroll
        for (int p = 0; p < 5; p++) {
            const float2 v01 = unpack2(c01[p]);
            const float2 v23 = unpack2(c23[p]);
            pool0 += fmaxf(v01.x, 0.f);
            pool1 += fmaxf(v01.y, 0.f);
            pool2 += fmaxf(v23.x, 0.f);
            pool3 += fmaxf(v23.y, 0.f);
        }
        __syncthreads();   // before next chunk overwrites xs/h1d
    }

    // cross-p-group reduction (reuse h1d as float[4][256])
    {
        float* rb = (float*)h1d;
        rb[pg * H1 + j0 + 0] = pool0;
        rb[pg * H1 + j0 + 1] = pool1;
        rb[pg * H1 + j0 + 2] = pool2;
        rb[pg * H1 + j0 + 3] = pool3;
        __syncthreads();
        const float s = (rb[tid] + rb[256 + tid] + rb[512 + tid] + rb[768 + tid]) * 0.01f;
        g_pooled[(size_t)b * H2 + tid] = s;
    }
}

// ---------------------------------------------------------------------------
// Kernel 2: fc3..fc6 head. 8 samples per CTA, 256 threads. (unchanged)
// ---------------------------------------------------------------------------
__global__ __launch_bounds__(256) void head_kernel(
    const float* __restrict__ c,
    const float* __restrict__ w3, const float* __restrict__ b3,
    const float* __restrict__ w4, const float* __restrict__ b4,
    const float* __restrict__ w5, const float* __restrict__ b5,
    const float* __restrict__ w6, const float* __restrict__ b6)
{
    __shared__ float zin[8 * F3IN];   // 10240 B
    __shared__ float h3 [8 * F3OUT];  // 16384 B
    __shared__ float h4 [8 * F4OUT];  //  8192 B
    __shared__ float h5 [8 * F5OUT];  //  4096 B

    const int bb  = blockIdx.x * 8;
    const int tid = threadIdx.x;

    for (int i = tid; i < 8 * CTX; i += 256) {
        const int s = i >> 6, k = i & 63;
        zin[s * F3IN + k] = c[(size_t)(bb + s) * CTX + k];
    }
    for (int i = tid; i < 8 * H2; i += 256) {
        const int s = i >> 8, k = i & 255;
        zin[s * F3IN + CTX + k] = g_pooled[(size_t)(bb + s) * H2 + k];
    }
    __syncthreads();

    // fc3: 320 -> 512
    {
        const int j0 = tid * 2;
        const float2 bv = *(const float2*)(b3 + j0);
        float2 acc[8];
        #pragma unroll
        for (int s = 0; s < 8; s++) acc[s] = bv;
        #pragma unroll 4
        for (int k = 0; k < F3IN; k++) {
            const float2 w = *(const float2*)(w3 + k * F3OUT + j0);
            #pragma unroll
            for (int s = 0; s < 8; s++) {
                const float zv = zin[s * F3IN + k];
                acc[s].x = fmaf(zv, w.x, acc[s].x);
                acc[s].y = fmaf(zv, w.y, acc[s].y);
            }
        }
        #pragma unroll
        for (int s = 0; s < 8; s++) {
            float2 r;
            r.x = fmaxf(acc[s].x, 0.f);
            r.y = fmaxf(acc[s].y, 0.f);
            *(float2*)(h3 + s * F3OUT + j0) = r;
        }
    }
    __syncthreads();

    // fc4: 512 -> 256
    {
        const float bv = b4[tid];
        float acc[8];
        #pragma unroll
        for (int s = 0; s < 8; s++) acc[s] = bv;
        #pragma unroll 8
        for (int k = 0; k < F3OUT; k++) {
            const float w = w4[k * F4OUT + tid];
            #pragma unroll
            for (int s = 0; s < 8; s++) acc[s] = fmaf(h3[s * F3OUT + k], w, acc[s]);
        }
        #pragma unroll
        for (int s = 0; s < 8; s++) h4[s * F4OUT + tid] = fmaxf(acc[s], 0.f);
    }
    __syncthreads();

    // fc5: 256 -> 128
    {
        const int j  = tid & 127;
        const int sh = tid >> 7;
        const float bv = b5[j];
        float acc[4];
        #pragma unroll
        for (int i = 0; i < 4; i++) acc[i] = bv;
        #pragma unroll 8
        for (int k = 0; k < F4OUT; k++) {
            const float w = w5[k * F5OUT + j];
            #pragma unroll
            for (int i = 0; i < 4; i++)
                acc[i] = fmaf(h4[(sh * 4 + i) * F4OUT + k], w, acc[i]);
        }
        #pragma unroll
        for (int i = 0; i < 4; i++) h5[(sh * 4 + i) * F5OUT + j] = fmaxf(acc[i], 0.f);
    }
    __syncthreads();

    // fc6: 128 -> 32
    {
        const int s = tid >> 5, j = tid & 31;
        float acc = b6[j];
        #pragma unroll 8
        for (int k = 0; k < F5OUT; k++)
            acc = fmaf(h5[s * F5OUT + k], w6[k * F6OUT + j], acc);
        g_z[(size_t)(bb + s) * F6OUT + j] = fmaxf(acc, 0.f);
    }
}

// ---------------------------------------------------------------------------
// Kernel 3: 24-step 6-layer LSTM rollout + logits + top-8 per step. (unchanged)
// ---------------------------------------------------------------------------
__device__ __forceinline__ float sigmoidf_(float v) { return 1.0f / (1.0f + expf(-v)); }

__global__ __launch_bounds__(256) void lstm_kernel(
    const float* __restrict__ hidden0, const float* __restrict__ cell0,
    const float* __restrict__ wih, const float* __restrict__ whh,
    const float* __restrict__ bih, const float* __restrict__ bhh,
    const float* __restrict__ w10, const float* __restrict__ b10,
    float* __restrict__ out)
{
    __shared__ float hst[NLAYER * 8 * HID];   // 6144 B
    __shared__ float cst[NLAYER * 8 * HID];   // 6144 B
    __shared__ float xb [8 * HID];            // 1024 B
    __shared__ float gsm[8 * 128];            // 4096 B
    __shared__ float lsm[8 * 368];            // 11776 B
    __shared__ float bsum[NLAYER * 128];      // 3072 B

    const int bbase = blockIdx.x * 8;
    const int tid   = threadIdx.x;

    for (int i = tid; i < NLAYER * 8 * HID; i += 256) {
        const int l = i >> 8;
        const int r = i & 255;
        hst[i] = hidden0[(size_t)l * BATCH * HID + (size_t)bbase * HID + r];
        cst[i] = cell0  [(size_t)l * BATCH * HID + (size_t)bbase * HID + r];
    }
    for (int i = tid; i < 8 * HID; i += 256) xb[i] = g_z[(size_t)bbase * HID + i];
    for (int i = tid; i < NLAYER * 128; i += 256) bsum[i] = bih[i] + bhh[i];
    __syncthreads();

    const int jg = tid & 31, sg = tid >> 5;
    const int j0 = jg * 4;
    const int lane = tid & 31, warp = tid >> 5;

    const float* inp = xb;   // scan carry

    for (int t = 0; t < TSTEPS; t++) {
        const float* lin = inp;
        for (int l = 0; l < NLAYER; l++) {
            float4 a = *(const float4*)(bsum + l * 128 + j0);
            const float* Wi = wih + (size_t)l * HID * 128;
            const float* Wh = whh + (size_t)l * HID * 128;
            const float* ip = lin + sg * HID;
            const float* hp = hst + l * 8 * HID + sg * HID;
            #pragma unroll
            for (int k = 0; k < HID; k++) {
                const float4 w = *(const float4*)(Wi + k * 128 + j0);
                const float xv = ip[k];
                a.x = fmaf(xv, w.x, a.x); a.y = fmaf(xv, w.y, a.y);
                a.z = fmaf(xv, w.z, a.z); a.w = fmaf(xv, w.w, a.w);
            }
            #pragma unroll
            for (int k = 0; k < HID; k++) {
                const float4 w = *(const float4*)(Wh + k * 128 + j0);
                const float hv = hp[k];
                a.x = fmaf(hv, w.x, a.x); a.y = fmaf(hv, w.y, a.y);
                a.z = fmaf(hv, w.z, a.z); a.w = fmaf(hv, w.w, a.w);
            }
            *(float4*)(gsm + sg * 128 + j0) = a;
            __syncthreads();

            {
                const int s = tid >> 5, u = tid & 31;
                const float ig = sigmoidf_(gsm[s * 128 + u]);
                const float fg = sigmoidf_(gsm[s * 128 + 32 + u]);
                const float gg = tanhf    (gsm[s * 128 + 64 + u]);
                const float og = sigmoidf_(gsm[s * 128 + 96 + u]);
                const int ci = l * 8 * HID + s * HID + u;
                const float cn = fmaf(fg, cst[ci], ig * gg);
                cst[ci] = cn;
                hst[ci] = og * tanhf(cn);
            }
            __syncthreads();
            lin = hst + l * 8 * HID;
        }
        inp = hst + 5 * 8 * HID;   // carry to next timestep

        // logits
        {
            const float* h5v = hst + 5 * 8 * HID;
            const int v  = tid;
            const int v2 = tid + 256;
            const bool has2 = (v2 < VOCAB);
            float acc[8], acc2[8];
            const float bv  = b10[v];
            const float bv2 = has2 ? b10[v2] : 0.f;
            #pragma unroll
            for (int s = 0; s < 8; s++) { acc[s] = bv; acc2[s] = bv2; }
            #pragma unroll
            for (int k = 0; k < HID; k++) {
                const float w  = w10[k * VOCAB + v];
                const float w2 = has2 ? w10[k * VOCAB + v2] : 0.f;
                #pragma unroll
                for (int s = 0; s < 8; s++) {
                    const float hv = h5v[s * HID + k];
                    acc[s]  = fmaf(hv, w,  acc[s]);
                    acc2[s] = fmaf(hv, w2, acc2[s]);
                }
            }
            #pragma unroll
            for (int s = 0; s < 8; s++) {
                lsm[s * 368 + v] = acc[s];
                if (has2) lsm[s * 368 + v2] = acc2[s];
            }
        }
        __syncthreads();

        // top-8: one warp per sample, stable tie-break (lower index wins)
        {
            const int s = warp;
            float vals[12];
            #pragma unroll
            for (int i = 0; i < 12; i++) {
                const int idx = lane + i * 32;
                vals[i] = (idx < VOCAB) ? lsm[s * 368 + idx] : -FLT_MAX;
            }
            const int obase = (bbase + s) * (TSTEPS * TOPK) + t * TOPK;
            #pragma unroll
            for (int r = 0; r < TOPK; r++) {
                float bvv = vals[0]; int bi = 0;
                #pragma unroll
                for (int i = 1; i < 12; i++)
                    if (vals[i] > bvv) { bvv = vals[i]; bi = i; }
                int gi = lane + bi * 32;
                #pragma unroll
                for (int off = 16; off; off >>= 1) {
                    const float ov = __shfl_xor_sync(0xffffffffu, bvv, off);
                    const int   oi = __shfl_xor_sync(0xffffffffu, gi,  off);
                    if (ov > bvv || (ov == bvv && oi < gi)) { bvv = ov; gi = oi; }
                }
                if (lane == 0) out[obase + r] = (float)gi;   // FLOAT output
                if ((gi & 31) == lane) vals[gi >> 5] = -FLT_MAX;
            }
        }
        __syncthreads();
    }
}

// ---------------------------------------------------------------------------
// Host: identify inputs BY SIZE (element count or bytes auto-detected).
// ---------------------------------------------------------------------------
extern "C" void kernel_launch(void* const* d_in, const int* in_sizes, int n_in,
                              void* d_out, int out_size)
{
    const float* C_=0; const float* X_=0; const float* HID0_=0; const float* CELL0_=0;
    const float* W1_=0; const float* B1_=0; const float* W2_=0; const float* B2_=0;
    const float* W3_=0; const float* B3_=0; const float* W4_=0; const float* B4_=0;
    const float* W5_=0; const float* B5_=0; const float* W6_=0; const float* B6_=0;
    const float* BIH_=0; const float* BHH_=0; const float* W10_=0; const float* B10_=0;

    int div = 1;
    for (int i = 0; i < n_in; i++) {
        if (in_sizes[i] == 26214400) { div = 1; break; }
        if (in_sizes[i] == 104857600) { div = 4; break; }
    }

    int n256 = 0, n786 = 0, n768 = 0, n24k = 0;
    int idx24k[2] = {-1, -1};
    int idx_fc10w = -1, idx_fc1w = -1;

    for (int i = 0; i < n_in; i++) {
        const long s = (long)in_sizes[i] / div;
        const float* p = (const float*)d_in[i];
        switch (s) {
            case 262144:   C_  = p; break;
            case 26214400: X_  = p; break;
            case 786432:   if (n786++ == 0) HID0_ = p; else CELL0_ = p; break;
            case 16384:    W1_ = p; idx_fc1w = i; break;
            case 256:      { if (n256 == 0) B1_ = p; else if (n256 == 1) B2_ = p;
                             else B4_ = p; n256++; } break;
            case 65536:    W2_ = p; break;
            case 163840:   W3_ = p; break;
            case 512:      B3_ = p; break;
            case 131072:   W4_ = p; break;
            case 32768:    W5_ = p; break;
            case 128:      B5_ = p; break;
            case 4096:     W6_ = p; break;
            case 32:       B6_ = p; break;
            case 24576:    if (n24k < 2) idx24k[n24k] = i; n24k++; break;
            case 768:      if (n768++ == 0) BIH_ = p; else BHH_ = p; break;
            case 11552:    W10_ = p; idx_fc10w = i; break;
            case 361:      B10_ = p; break;
            default: break; // particle_size scalar etc.
        }
    }

    const float* WIH_ = 0; const float* WHH_ = 0;
    if (n24k >= 2) {
        const bool alpha = (idx_fc10w >= 0 && idx_fc1w >= 0 && idx_fc10w < idx_fc1w);
        const int wih_idx = alpha ? idx24k[1] : idx24k[0];
        const int whh_idx = alpha ? idx24k[0] : idx24k[1];
        WIH_ = (const float*)d_in[wih_idx];
        WHH_ = (const float*)d_in[whh_idx];
    }

    if (!C_ || !X_ || !HID0_ || !CELL0_ || !W1_ || !B1_ || !W2_ || !B2_ ||
        !W3_ || !B3_ || !W4_ || !B4_ || !W5_ || !B5_ || !W6_ || !B6_ ||
        !WIH_ || !WHH_ || !BIH_ || !BHH_ || !W10_ || !B10_) {
        C_    = (const float*)d_in[0];  X_    = (const float*)d_in[1];
        HID0_ = (const float*)d_in[2];  CELL0_= (const float*)d_in[3];
        W1_   = (const float*)d_in[4];  B1_   = (const float*)d_in[5];
        W2_   = (const float*)d_in[6];  B2_   = (const float*)d_in[7];
        W3_   = (const float*)d_in[8];  B3_   = (const float*)d_in[9];
        W4_   = (const float*)d_in[10]; B4_   = (const float*)d_in[11];
        W5_   = (const float*)d_in[12]; B5_   = (const float*)d_in[13];
        W6_   = (const float*)d_in[14]; B6_   = (const float*)d_in[15];
        WIH_  = (const float*)d_in[16]; WHH_  = (const float*)d_in[17];
        BIH_  = (const float*)d_in[18]; BHH_  = (const float*)d_in[19];
        W10_  = (const float*)d_in[20]; B10_  = (const float*)d_in[21];
    }
    (void)out_size;

    enc_kernel<<<BATCH, 256>>>(X_, W1_, B1_, W2_, B2_);
    head_kernel<<<BATCH / 8, 256>>>(C_, W3_, B3_, W4_, B4_, W5_, B5_, W6_, B6_);
    lstm_kernel<<<BATCH / 8, 256>>>(HID0_, CELL0_, WIH_, WHH_, BIH_, BHH_,
                                    W10_, B10_, (float*)d_out);
}